// round 9
// baseline (speedup 1.0000x reference)
#include <cuda_runtime.h>
#include <cuda_bf16.h>
#include <cstdint>

// Problem constants
#define BSZ 4
#define TLEN 2048
#define CDIM 1024
#define NH 16
#define HD 64
#define MTOT (BSZ * TLEN)        // 8192
#define N_QKV (3 * CDIM)         // 3072
#define KDIM 1024
#define ATT_SCALE 0.125f

// ---------------------------------------------------------------------------
// Scratch (__device__ globals; referenced ONLY inside device code)
// ---------------------------------------------------------------------------
__device__ __nv_bfloat16 g_qh[(size_t)BSZ * NH * TLEN * HD];
__device__ __nv_bfloat16 g_ql[(size_t)BSZ * NH * TLEN * HD];
__device__ __nv_bfloat16 g_kh[(size_t)BSZ * NH * TLEN * HD];
__device__ __nv_bfloat16 g_kl[(size_t)BSZ * NH * TLEN * HD];
__device__ __nv_bfloat16 g_vh[(size_t)BSZ * NH * TLEN * HD];
__device__ __nv_bfloat16 g_vl[(size_t)BSZ * NH * TLEN * HD];
__device__ __nv_bfloat16 g_xh[(size_t)MTOT * CDIM];
__device__ __nv_bfloat16 g_xl[(size_t)MTOT * CDIM];
__device__ __nv_bfloat16 g_wqh[(size_t)N_QKV * CDIM];
__device__ __nv_bfloat16 g_wql[(size_t)N_QKV * CDIM];
__device__ __nv_bfloat16 g_woh[(size_t)CDIM * CDIM];
__device__ __nv_bfloat16 g_wol[(size_t)CDIM * CDIM];
__device__ __nv_bfloat16 g_atth[(size_t)MTOT * CDIM];
__device__ __nv_bfloat16 g_attl[(size_t)MTOT * CDIM];

// ---------------------------------------------------------------------------
// Helpers
// ---------------------------------------------------------------------------
__device__ __forceinline__ uint32_t smem_u32(const void* p) {
    uint32_t a;
    asm("{ .reg .u64 t; cvta.to.shared.u64 t, %1; cvt.u32.u64 %0, t; }"
        : "=r"(a) : "l"(p));
    return a;
}

__device__ __forceinline__ void mma16816(float c[4], uint32_t a0, uint32_t a1,
                                         uint32_t a2, uint32_t a3,
                                         uint32_t b0, uint32_t b1) {
    asm volatile(
        "mma.sync.aligned.m16n8k16.row.col.f32.bf16.bf16.f32 "
        "{%0,%1,%2,%3}, {%4,%5,%6,%7}, {%8,%9}, {%0,%1,%2,%3};"
        : "+f"(c[0]), "+f"(c[1]), "+f"(c[2]), "+f"(c[3])
        : "r"(a0), "r"(a1), "r"(a2), "r"(a3), "r"(b0), "r"(b1));
}

__device__ __forceinline__ void ldm_x4(uint32_t r[4], uint32_t addr) {
    asm volatile("ldmatrix.sync.aligned.m8n8.x4.shared.b16 {%0,%1,%2,%3}, [%4];"
                 : "=r"(r[0]), "=r"(r[1]), "=r"(r[2]), "=r"(r[3]) : "r"(addr));
}
__device__ __forceinline__ void ldm_x4_t(uint32_t r[4], uint32_t addr) {
    asm volatile("ldmatrix.sync.aligned.m8n8.x4.trans.shared.b16 {%0,%1,%2,%3}, [%4];"
                 : "=r"(r[0]), "=r"(r[1]), "=r"(r[2]), "=r"(r[3]) : "r"(addr));
}

#define CP16(sa, gp) \
    asm volatile("cp.async.cg.shared.global [%0], [%1], 16;" :: "r"(sa), "l"(gp))
#define CP_COMMIT() asm volatile("cp.async.commit_group;" ::: "memory")
#define CP_WAIT0()  asm volatile("cp.async.wait_group 0;" ::: "memory")
#define CP_WAIT1()  asm volatile("cp.async.wait_group 1;" ::: "memory")

// RN pack (LO parts only)
__device__ __forceinline__ uint32_t cvt2bf(float lo_val, float hi_val) {
    uint32_t r;
    asm("cvt.rn.bf16x2.f32 %0, %1, %2;" : "=r"(r) : "f"(hi_val), "f"(lo_val));
    return r;
}
// TRUNC pack (HI parts; consistent with residual)
__device__ __forceinline__ uint32_t trunc2bf(float a, float b) {
    return __byte_perm(__float_as_uint(a), __float_as_uint(b), 0x7632);
}
__device__ __forceinline__ float bf16res(float v) {
    return v - __uint_as_float(__float_as_uint(v) & 0xFFFF0000u);
}
__device__ __forceinline__ void split4(float4 v, uint2& hv, uint2& lv) {
    uint32_t bx = __float_as_uint(v.x), by = __float_as_uint(v.y);
    uint32_t bz = __float_as_uint(v.z), bw = __float_as_uint(v.w);
    hv.x = __byte_perm(bx, by, 0x7632);
    hv.y = __byte_perm(bz, bw, 0x7632);
    lv.x = cvt2bf(bf16res(v.x), bf16res(v.y));
    lv.y = cvt2bf(bf16res(v.z), bf16res(v.w));
}

// ---------------------------------------------------------------------------
// One-time split: fp32 -> (bf16 hi, bf16 lo) for x, w_qkv, w_out
// ---------------------------------------------------------------------------
#define NX  ((size_t)MTOT * CDIM)
#define NWQ ((size_t)N_QKV * CDIM)
#define NWO ((size_t)CDIM * CDIM)
#define NSPLIT4 ((NX + NWQ + NWO) / 4)

__global__ __launch_bounds__(256) void split_in(const float* __restrict__ x,
                                                const float* __restrict__ wq,
                                                const float* __restrict__ wo) {
    size_t i4 = (size_t)blockIdx.x * 256 + threadIdx.x;
    if (i4 >= NSPLIT4) return;
    size_t e = i4 * 4;
    const float* s;
    __nv_bfloat16 *dh, *dl;
    if (e < NX) { s = x + e; dh = g_xh + e; dl = g_xl + e; }
    else if (e < NX + NWQ) { size_t l = e - NX; s = wq + l; dh = g_wqh + l; dl = g_wql + l; }
    else { size_t l = e - NX - NWQ; s = wo + l; dh = g_woh + l; dl = g_wol + l; }
    float4 v = *(const float4*)s;
    uint2 hv, lv;
    split4(v, hv, lv);
    *(uint2*)dh = hv;
    *(uint2*)dl = lv;
}

// ---------------------------------------------------------------------------
// mma.sync bf16x3 GEMM, cp.async 2-stage pipelined, bf16 hi/lo inputs.
// C[M,N] = A[M,K] @ B[N,K]^T. BM=BN=128, BK=32, 256 thr, 8 warps.
// epi=0: A=x(split), B=w_qkv(split); write Q(scaled)/K/V bf16 hi/lo [bh][t][d].
// epi=1: A=att(split), B=w_out(split); write fp32 out + bias.
// ---------------------------------------------------------------------------
#define GBK 32
#define ALDS 40
#define TILE_B (2 * 128 * ALDS)       // 10240 bytes per tile
#define STAGE_B (4 * TILE_B)          // 40960
#define MM_SMEM (2 * STAGE_B)         // 81920

__global__ __launch_bounds__(256) void mm_kernel(
    const float* __restrict__ bias, float* __restrict__ out, int epi) {
    extern __shared__ __align__(16) uint16_t smbuf[];
    const int tid = threadIdx.x;
    const int lane = tid & 31, w = tid >> 5;
    const int wm = w & 3, wn = w >> 2;
    const int bm = blockIdx.y, bn = blockIdx.x;

    const __nv_bfloat16 *tp[4];
    if (epi == 0) { tp[0] = g_xh; tp[1] = g_xl; tp[2] = g_wqh; tp[3] = g_wql; }
    else          { tp[0] = g_atth; tp[1] = g_attl; tp[2] = g_woh; tp[3] = g_wol; }
    const __nv_bfloat16* base_[4];
#pragma unroll
    for (int i = 0; i < 4; i++)
        base_[i] = tp[i] + (size_t)(i < 2 ? bm : bn) * 128 * KDIM;

    float c[2][8][4];
#pragma unroll
    for (int i = 0; i < 2; i++)
#pragma unroll
        for (int j = 0; j < 8; j++)
#pragma unroll
            for (int k = 0; k < 4; k++) c[i][j][k] = 0.f;

    const uint32_t smb = smem_u32(smbuf);

    auto load_stage = [&](int st, int kt) {
#pragma unroll
        for (int j = 0; j < 8; j++) {
            int q = tid + j * 256;
            int tile = q >> 9;
            int qq = q & 511;
            int r = qq >> 2;
            int c8 = (qq & 3) * 8;
            const __nv_bfloat16* src = base_[tile] + (size_t)r * KDIM + kt + c8;
            uint32_t sa = smb + st * STAGE_B + tile * TILE_B + 2 * (r * ALDS + c8);
            CP16(sa, src);
        }
        CP_COMMIT();
    };

    load_stage(0, 0);

    const int NIT = KDIM / GBK;        // 32
    for (int it = 0; it < NIT; it++) {
        const int p = it & 1;
        if (it + 1 < NIT) {
            load_stage(p ^ 1, (it + 1) * GBK);
            CP_WAIT1();
        } else {
            CP_WAIT0();
        }
        __syncthreads();

        const uint32_t sAh = smb + p * STAGE_B;
        const uint32_t sAl = sAh + TILE_B;
        const uint32_t sBh = sAh + 2 * TILE_B;
        const uint32_t sBl = sAh + 3 * TILE_B;

#pragma unroll
        for (int ks = 0; ks < 2; ks++) {
            uint32_t ah[2][4], al[2][4];
#pragma unroll
            for (int mi = 0; mi < 2; mi++) {
                uint32_t off = 2 * ((wm * 32 + 16 * mi + (lane & 15)) * ALDS +
                                    ks * 16 + (lane >> 4) * 8);
                ldm_x4(ah[mi], sAh + off);
                ldm_x4(al[mi], sAl + off);
            }
#pragma unroll
            for (int njp = 0; njp < 4; njp++) {
                int rowB = wn * 64 + njp * 16 + (lane & 7) + ((lane >> 4) & 1) * 8;
                uint32_t off = 2 * (rowB * ALDS + ks * 16 + ((lane >> 3) & 1) * 8);
                uint32_t bh4[4], bl4[4];
                ldm_x4(bh4, sBh + off);
                ldm_x4(bl4, sBl + off);
#pragma unroll
                for (int mi = 0; mi < 2; mi++) {
                    mma16816(c[mi][2 * njp], ah[mi][0], ah[mi][1], ah[mi][2], ah[mi][3], bh4[0], bh4[1]);
                    mma16816(c[mi][2 * njp], ah[mi][0], ah[mi][1], ah[mi][2], ah[mi][3], bl4[0], bl4[1]);
                    mma16816(c[mi][2 * njp], al[mi][0], al[mi][1], al[mi][2], al[mi][3], bh4[0], bh4[1]);
                    mma16816(c[mi][2 * njp + 1], ah[mi][0], ah[mi][1], ah[mi][2], ah[mi][3], bh4[2], bh4[3]);
                    mma16816(c[mi][2 * njp + 1], ah[mi][0], ah[mi][1], ah[mi][2], ah[mi][3], bl4[2], bl4[3]);
                    mma16816(c[mi][2 * njp + 1], al[mi][0], al[mi][1], al[mi][2], al[mi][3], bh4[2], bh4[3]);
                }
            }
        }
        __syncthreads();
    }

    const int rin = lane >> 2, col2 = (lane & 3) * 2;
#pragma unroll
    for (int mi = 0; mi < 2; mi++) {
#pragma unroll
        for (int h2 = 0; h2 < 2; h2++) {
            int m = bm * 128 + wm * 32 + mi * 16 + rin + h2 * 8;
#pragma unroll
            for (int nj = 0; nj < 8; nj++) {
                int n = bn * 128 + wn * 64 + nj * 8 + col2;
                float v0 = c[mi][nj][h2 * 2 + 0];
                float v1 = c[mi][nj][h2 * 2 + 1];
                if (epi == 0) {
                    int which = n >> 10;
                    int o = n & 1023;
                    int h = o >> 6, d = o & 63;
                    if (which == 0) { v0 *= ATT_SCALE; v1 *= ATT_SCALE; }
                    __nv_bfloat16 *dh, *dl;
                    if (which == 0) { dh = g_qh; dl = g_ql; }
                    else if (which == 1) { dh = g_kh; dl = g_kl; }
                    else { dh = g_vh; dl = g_vl; }
                    int bb = m >> 11, t = m & (TLEN - 1);
                    size_t idx = ((size_t)(bb * NH + h) * TLEN + t) * HD + d;
                    uint32_t hv = trunc2bf(v0, v1);
                    uint32_t lv = cvt2bf(bf16res(v0), bf16res(v1));
                    *(uint32_t*)(dh + idx) = hv;
                    *(uint32_t*)(dl + idx) = lv;
                } else {
                    float2 o2;
                    o2.x = v0 + bias[n];
                    o2.y = v1 + bias[n + 1];
                    *(float2*)(out + (size_t)m * CDIM + n) = o2;
                }
            }
        }
    }
}

// ---------------------------------------------------------------------------
// FA2 attention (causal) on mma.sync bf16x3. bf16 hi/lo inputs + outputs.
// CTA: 128 q-rows x one (b,h). 8 warps x 16 q-rows; kv tile 64.
// ---------------------------------------------------------------------------
#define ASTR 72
#define QH_OFF 0
#define QL_OFF (128 * ASTR)
#define KH_OFF (2 * 128 * ASTR)
#define KL_OFF (KH_OFF + 64 * ASTR)
#define VH_OFF (KL_OFF + 64 * ASTR)
#define VL_OFF (VH_OFF + 64 * ASTR)
#define AT_SMEM ((VL_OFF + 64 * ASTR) * 2)   // 73728 bytes

__global__ __launch_bounds__(256) void attn_kernel() {
    extern __shared__ __align__(16) uint16_t asmbuf[];
    const int tid = threadIdx.x;
    const int lane = tid & 31, w = tid >> 5;
    const int qt = blockIdx.x;           // 0..15
    const int bh = blockIdx.y;           // 0..63
    const uint32_t smb = smem_u32(asmbuf);

    // Q tile [128 x 64] hi/lo via cp.async (scale already folded in by mm1)
    {
        const size_t qb = ((size_t)bh * TLEN + qt * 128) * HD;
#pragma unroll
        for (int j = 0; j < 8; j++) {
            int q = tid + j * 256;
            int tile = q >> 10;              // 0:qh 1:ql
            int qq = q & 1023;
            int r = qq >> 3;
            int c8 = (qq & 7) * 8;
            const __nv_bfloat16* src = (tile == 0 ? g_qh : g_ql) + qb + (size_t)r * HD + c8;
            uint32_t sa = smb + 2 * ((tile == 0 ? QH_OFF : QL_OFF) + r * ASTR + c8);
            CP16(sa, src);
        }
        CP_COMMIT();
    }

    float co[8][4];
    float mrow[2] = {-1e30f, -1e30f};
    float lsum[2] = {0.f, 0.f};
#pragma unroll
    for (int j = 0; j < 8; j++)
#pragma unroll
        for (int k = 0; k < 4; k++) co[j][k] = 0.f;

    const int rin = lane >> 2, col2 = (lane & 3) * 2;
    const int kv_tiles = 2 * qt + 2;

    for (int kt = 0; kt < kv_tiles; kt++) {
        __syncthreads();   // smem reuse guard
        // K/V tiles [64 x 64] hi/lo via cp.async
        {
            const size_t kvb = ((size_t)bh * TLEN + kt * 64) * HD;
            const __nv_bfloat16* srcs[4] = {g_kh, g_kl, g_vh, g_vl};
            const int offs[4] = {KH_OFF, KL_OFF, VH_OFF, VL_OFF};
#pragma unroll
            for (int j = 0; j < 8; j++) {
                int q = tid + j * 256;
                int tile = q >> 9;
                int qq = q & 511;
                int r = qq >> 3;
                int c8 = (qq & 7) * 8;
                const __nv_bfloat16* src = srcs[tile] + kvb + (size_t)r * HD + c8;
                uint32_t sa = smb + 2 * (offs[tile] + r * ASTR + c8);
                CP16(sa, src);
            }
            CP_COMMIT();
            CP_WAIT0();
        }
        __syncthreads();

        // S = Q K^T (bf16x3)
        float cs[8][4];
#pragma unroll
        for (int j = 0; j < 8; j++)
#pragma unroll
            for (int k = 0; k < 4; k++) cs[j][k] = 0.f;

#pragma unroll
        for (int ks = 0; ks < 4; ks++) {
            uint32_t aoff = 2 * ((16 * w + (lane & 15)) * ASTR + ks * 16 + (lane >> 4) * 8);
            uint32_t aq_h[4], aq_l[4];
            ldm_x4(aq_h, smb + 2 * QH_OFF + aoff);
            ldm_x4(aq_l, smb + 2 * QL_OFF + aoff);
#pragma unroll
            for (int njp = 0; njp < 4; njp++) {
                int rowK = njp * 16 + (lane & 7) + ((lane >> 4) & 1) * 8;
                uint32_t boff = 2 * (rowK * ASTR + ks * 16 + ((lane >> 3) & 1) * 8);
                uint32_t bh4[4], bl4[4];
                ldm_x4(bh4, smb + 2 * KH_OFF + boff);
                ldm_x4(bl4, smb + 2 * KL_OFF + boff);
                mma16816(cs[2 * njp], aq_h[0], aq_h[1], aq_h[2], aq_h[3], bh4[0], bh4[1]);
                mma16816(cs[2 * njp], aq_h[0], aq_h[1], aq_h[2], aq_h[3], bl4[0], bl4[1]);
                mma16816(cs[2 * njp], aq_l[0], aq_l[1], aq_l[2], aq_l[3], bh4[0], bh4[1]);
                mma16816(cs[2 * njp + 1], aq_h[0], aq_h[1], aq_h[2], aq_h[3], bh4[2], bh4[3]);
                mma16816(cs[2 * njp + 1], aq_h[0], aq_h[1], aq_h[2], aq_h[3], bl4[2], bl4[3]);
                mma16816(cs[2 * njp + 1], aq_l[0], aq_l[1], aq_l[2], aq_l[3], bh4[2], bh4[3]);
            }
        }

        // Causal mask
        if (kt >= 2 * qt) {
#pragma unroll
            for (int nj = 0; nj < 8; nj++)
#pragma unroll
                for (int h2 = 0; h2 < 2; h2++) {
                    int qr = qt * 128 + 16 * w + rin + 8 * h2;
                    int kc = kt * 64 + nj * 8 + col2;
                    if (kc > qr) cs[nj][2 * h2] = -1e30f;
                    if (kc + 1 > qr) cs[nj][2 * h2 + 1] = -1e30f;
                }
        }

        // Online softmax
#pragma unroll
        for (int h2 = 0; h2 < 2; h2++) {
            float mx = -1e30f;
#pragma unroll
            for (int nj = 0; nj < 8; nj++) {
                mx = fmaxf(mx, cs[nj][2 * h2]);
                mx = fmaxf(mx, cs[nj][2 * h2 + 1]);
            }
            mx = fmaxf(mx, __shfl_xor_sync(0xffffffffu, mx, 1));
            mx = fmaxf(mx, __shfl_xor_sync(0xffffffffu, mx, 2));
            float mn = fmaxf(mrow[h2], mx);
            float alpha = __expf(mrow[h2] - mn);
            mrow[h2] = mn;
            float rs = 0.f;
#pragma unroll
            for (int nj = 0; nj < 8; nj++) {
                float p0 = __expf(cs[nj][2 * h2] - mn);
                float p1 = __expf(cs[nj][2 * h2 + 1] - mn);
                cs[nj][2 * h2] = p0;
                cs[nj][2 * h2 + 1] = p1;
                rs += p0 + p1;
            }
            rs += __shfl_xor_sync(0xffffffffu, rs, 1);
            rs += __shfl_xor_sync(0xffffffffu, rs, 2);
            lsum[h2] = lsum[h2] * alpha + rs;
#pragma unroll
            for (int nj = 0; nj < 8; nj++) {
                co[nj][2 * h2] *= alpha;
                co[nj][2 * h2 + 1] *= alpha;
            }
        }

        // O += P V (bf16x3); P frags: hi = TRUNC, lo = RN(residual)
#pragma unroll
        for (int kk = 0; kk < 4; kk++) {
            uint32_t ph[4], pl[4];
            ph[0] = trunc2bf(cs[2 * kk][0], cs[2 * kk][1]);
            ph[1] = trunc2bf(cs[2 * kk][2], cs[2 * kk][3]);
            ph[2] = trunc2bf(cs[2 * kk + 1][0], cs[2 * kk + 1][1]);
            ph[3] = trunc2bf(cs[2 * kk + 1][2], cs[2 * kk + 1][3]);
            pl[0] = cvt2bf(bf16res(cs[2 * kk][0]), bf16res(cs[2 * kk][1]));
            pl[1] = cvt2bf(bf16res(cs[2 * kk][2]), bf16res(cs[2 * kk][3]));
            pl[2] = cvt2bf(bf16res(cs[2 * kk + 1][0]), bf16res(cs[2 * kk + 1][1]));
            pl[3] = cvt2bf(bf16res(cs[2 * kk + 1][2]), bf16res(cs[2 * kk + 1][3]));
#pragma unroll
            for (int djp = 0; djp < 4; djp++) {
                int rowV = kk * 16 + (lane & 7) + ((lane >> 3) & 1) * 8;
                uint32_t voff = 2 * (rowV * ASTR + djp * 16 + (lane >> 4) * 8);
                uint32_t bv_h[4], bv_l[4];
                ldm_x4_t(bv_h, smb + 2 * VH_OFF + voff);
                ldm_x4_t(bv_l, smb + 2 * VL_OFF + voff);
                mma16816(co[2 * djp], ph[0], ph[1], ph[2], ph[3], bv_h[0], bv_h[1]);
                mma16816(co[2 * djp], ph[0], ph[1], ph[2], ph[3], bv_l[0], bv_l[1]);
                mma16816(co[2 * djp], pl[0], pl[1], pl[2], pl[3], bv_h[0], bv_h[1]);
                mma16816(co[2 * djp + 1], ph[0], ph[1], ph[2], ph[3], bv_h[2], bv_h[3]);
                mma16816(co[2 * djp + 1], ph[0], ph[1], ph[2], ph[3], bv_l[2], bv_l[3]);
                mma16816(co[2 * djp + 1], pl[0], pl[1], pl[2], pl[3], bv_h[2], bv_h[3]);
            }
        }
    }

    // Epilogue: normalize, split hi/lo, write bf16 to g_atth/g_attl
    const int b = bh >> 4, h = bh & 15;
#pragma unroll
    for (int h2 = 0; h2 < 2; h2++) {
        float inv = 1.f / lsum[h2];
        int t = qt * 128 + 16 * w + rin + 8 * h2;
        size_t base = ((size_t)b * TLEN + t) * CDIM + h * 64;
#pragma unroll
        for (int nj = 0; nj < 8; nj++) {
            int d = nj * 8 + col2;
            float v0 = co[nj][2 * h2] * inv;
            float v1 = co[nj][2 * h2 + 1] * inv;
            *(uint32_t*)(g_atth + base + d) = trunc2bf(v0, v1);
            *(uint32_t*)(g_attl + base + d) = cvt2bf(bf16res(v0), bf16res(v1));
        }
    }
}

// ---------------------------------------------------------------------------
extern "C" void kernel_launch(void* const* d_in, const int* in_sizes, int n_in,
                              void* d_out, int out_size) {
    const float* x = (const float*)d_in[0];
    const float* w_qkv = (const float*)d_in[1];
    const float* w_out = (const float*)d_in[2];
    const float* b_out = (const float*)d_in[3];
    float* out = (float*)d_out;

    cudaFuncSetAttribute(mm_kernel, cudaFuncAttributeMaxDynamicSharedMemorySize,
                         MM_SMEM);
    cudaFuncSetAttribute(attn_kernel, cudaFuncAttributeMaxDynamicSharedMemorySize,
                         AT_SMEM);

    // 0) one-time split fp32 -> bf16 hi/lo (x, w_qkv, w_out)
    split_in<<<(unsigned)((NSPLIT4 + 255) / 256), 256>>>(x, w_qkv, w_out);

    // 1) QKV projection (pipelined bf16x3) -> Q(scaled)/K/V bf16 hi/lo
    mm_kernel<<<dim3(N_QKV / 128, MTOT / 128), 256, MM_SMEM>>>(nullptr, nullptr, 0);

    // 2) FA2 attention (bf16x3) -> g_atth/g_attl
    attn_kernel<<<dim3(TLEN / 128, BSZ * NH), 256, AT_SMEM>>>();

    // 3) Output projection + bias (pipelined bf16x3) -> fp32 out
    mm_kernel<<<dim3(CDIM / 128, MTOT / 128), 256, MM_SMEM>>>(b_out, out, 1);
}